// round 13
// baseline (speedup 1.0000x reference)
#include <cuda_runtime.h>
#include <cstdint>

#define IN_CH  128
#define K_HOPS 3
#define MAX_N  10240
#define MAX_E  330000

#define TN     80          // nodes per GEMM block -> 125 blocks (single wave)

// Scratch (__device__ globals: allocation-guard-safe)
__device__ float  g_agg[(size_t)MAX_N * K_HOPS * IN_CH];   // [n][k][c] 15.7 MB
__device__ float4 g_packed[MAX_E];      // {x0,x1,x2, bits(dst)} sorted by src
__device__ int    g_rank[MAX_E];
__device__ int    g_cnt[MAX_N + 1];
__device__ int    g_off[MAX_N + 1];
__device__ int    g_is64;
// W in i-paired layout: g_wp[hop][i/2][o][parity] = W[hop][2*(i/2)+parity][o]
__device__ float  g_wp[3 * IN_CH * IN_CH];

// ---------------------------------------------------------------------------
// f32x2 packed helpers (PTX ISA 8.6, sm_100+) and cp.async helpers (Ampere+)
// ---------------------------------------------------------------------------
__device__ __forceinline__ void ffma2(uint64_t& c, uint64_t a, uint64_t b) {
    asm("fma.rn.f32x2 %0, %1, %2, %0;" : "+l"(c) : "l"(a), "l"(b));
}
__device__ __forceinline__ uint32_t smem_u32(const void* p) {
    uint32_t a;
    asm("{ .reg .u64 t; cvta.to.shared.u64 t, %1; cvt.u32.u64 %0, t; }"
        : "=r"(a) : "l"(p));
    return a;
}
__device__ __forceinline__ void cp_async16(uint32_t dst, const void* src) {
    asm volatile("cp.async.ca.shared.global [%0], [%1], 16;"
                 :: "r"(dst), "l"(src) : "memory");
}
#define CP_COMMIT()  asm volatile("cp.async.commit_group;" ::: "memory")
#define CP_WAIT(n)   asm volatile("cp.async.wait_group %0;" :: "n"(n) : "memory")

// ---------------------------------------------------------------------------
// Kernel 1: zero counts + detect edge_index dtype (JAX may emit int32 even
// though the reference asks for int64).
// ---------------------------------------------------------------------------
__global__ void init_kernel(const void* ei, int E, int N) {
    int i = blockIdx.x * blockDim.x + threadIdx.x;
    if (i <= N) g_cnt[i] = 0;
    if (i == 0) {
        const long long* p64 = (const long long*)ei;
        int ok = 1;
        int cnt = (E < 64) ? E : 64;
        for (int j = 0; j < cnt; j++) {
            long long v = p64[j];
            if (v < 0 || v >= (long long)N) { ok = 0; break; }
        }
        g_is64 = ok;
    }
}

// ---------------------------------------------------------------------------
// Kernel 1b: prepack W into i-paired layout for f32x2 b-operands.
//   g_wp[hop*16384 + ip*256 + o*2 + p] = W[hop][2*ip+p][o]
// ---------------------------------------------------------------------------
__global__ __launch_bounds__(256) void wprep_kernel(const float* __restrict__ W) {
    int t = blockIdx.x * blockDim.x + threadIdx.x;    // 3*64*128 = 24576
    if (t >= 3 * 64 * IN_CH) return;
    int hop = t / (64 * IN_CH);
    int rem = t % (64 * IN_CH);
    int ip  = rem >> 7;          // 0..63
    int o   = rem & 127;
    float w0 = __ldg(W + (size_t)hop * IN_CH * IN_CH + (size_t)(2 * ip) * IN_CH + o);
    float w1 = __ldg(W + (size_t)hop * IN_CH * IN_CH + (size_t)(2 * ip + 1) * IN_CH + o);
    float2* dst = reinterpret_cast<float2*>(g_wp + (size_t)hop * IN_CH * IN_CH + ip * 256);
    dst[o] = make_float2(w0, w1);
}

// ---------------------------------------------------------------------------
// Kernel 2: histogram of src + per-edge rank (atomic kept out of permute)
// ---------------------------------------------------------------------------
__global__ __launch_bounds__(256) void count_kernel(const void* __restrict__ ei,
                                                    int E, int N) {
    int e = blockIdx.x * blockDim.x + threadIdx.x;
    if (e >= E) return;
    int src = g_is64 ? (int)__ldg((const long long*)ei + e)
                     : __ldg((const int*)ei + e);
    if ((unsigned)src < (unsigned)N)
        g_rank[e] = atomicAdd(&g_cnt[src], 1);
}

// ---------------------------------------------------------------------------
// Kernel 3: exclusive scan (single block) -> offsets
// ---------------------------------------------------------------------------
__global__ __launch_bounds__(1024) void scan_kernel(int N) {
    __shared__ int part[1024];
    int t = threadIdx.x;
    int chunk = (N + 1023) / 1024;
    int b0 = t * chunk;
    int b1 = b0 + chunk; if (b1 > N) b1 = N;
    int s = 0;
    for (int i = b0; i < b1; i++) s += g_cnt[i];
    part[t] = s;
    __syncthreads();
    for (int off = 1; off < 1024; off <<= 1) {
        int add = (t >= off) ? part[t - off] : 0;
        __syncthreads();
        part[t] += add;
        __syncthreads();
    }
    int run = part[t] - s;
    for (int i = b0; i < b1; i++) { g_off[i] = run; run += g_cnt[i]; }
    if (t == 1023) g_off[N] = part[1023];
}

// ---------------------------------------------------------------------------
// Kernel 4: permute edges into src-sorted packed records (atomic-free)
// ---------------------------------------------------------------------------
__global__ __launch_bounds__(256) void permute_kernel(const void* __restrict__ ei,
                                                      const float* __restrict__ X,
                                                      int E, int N) {
    int e = blockIdx.x * blockDim.x + threadIdx.x;
    if (e >= E) return;
    int src, dst;
    if (g_is64) {
        const long long* p = (const long long*)ei;
        src = (int)__ldg(p + e);
        dst = (int)__ldg(p + (size_t)E + e);
    } else {
        const int* p = (const int*)ei;
        src = __ldg(p + e);
        dst = __ldg(p + (size_t)E + e);
    }
    if ((unsigned)src >= (unsigned)N || (unsigned)dst >= (unsigned)N) return;
    float x0 = __ldg(X + (size_t)e * 3 + 0);
    float x1 = __ldg(X + (size_t)e * 3 + 1);
    float x2 = __ldg(X + (size_t)e * 3 + 2);
    int pos = __ldg(&g_off[src]) + __ldg(&g_rank[e]);
    g_packed[pos] = make_float4(x0, x1, x2, __int_as_float(dst));
}

// ---------------------------------------------------------------------------
// Kernel 5: gather-aggregate.  One warp per node; lane owns 4 channels.
// 4-edge unroll for MLP.  Writes every node -> no zero pass needed.
// ---------------------------------------------------------------------------
__global__ __launch_bounds__(256) void gather_kernel(
    const float* __restrict__ h, int N) {
    int w    = (blockIdx.x * blockDim.x + threadIdx.x) >> 5;
    int lane = threadIdx.x & 31;
    if (w >= N) return;

    int beg = __ldg(&g_off[w]);
    int end = __ldg(&g_off[w + 1]);

    float4 a0 = make_float4(0.f, 0.f, 0.f, 0.f);
    float4 a1 = a0, a2 = a0;

    int e = beg;
    for (; e + 3 < end; e += 4) {
        float4 p[4];
        #pragma unroll
        for (int j = 0; j < 4; j++) p[j] = __ldg(&g_packed[e + j]);
        float4 hv[4];
        #pragma unroll
        for (int j = 0; j < 4; j++) {
            int d = __float_as_int(p[j].w);
            hv[j] = __ldg(reinterpret_cast<const float4*>(h + (size_t)d * IN_CH) + lane);
        }
        #pragma unroll
        for (int j = 0; j < 4; j++) {
            a0.x += p[j].x*hv[j].x; a0.y += p[j].x*hv[j].y; a0.z += p[j].x*hv[j].z; a0.w += p[j].x*hv[j].w;
            a1.x += p[j].y*hv[j].x; a1.y += p[j].y*hv[j].y; a1.z += p[j].y*hv[j].z; a1.w += p[j].y*hv[j].w;
            a2.x += p[j].z*hv[j].x; a2.y += p[j].z*hv[j].y; a2.z += p[j].z*hv[j].z; a2.w += p[j].z*hv[j].w;
        }
    }
    for (; e < end; e++) {
        float4 p0 = __ldg(&g_packed[e]);
        int d0 = __float_as_int(p0.w);
        float4 h0 = __ldg(reinterpret_cast<const float4*>(h + (size_t)d0 * IN_CH) + lane);
        a0.x += p0.x*h0.x; a0.y += p0.x*h0.y; a0.z += p0.x*h0.z; a0.w += p0.x*h0.w;
        a1.x += p0.y*h0.x; a1.y += p0.y*h0.y; a1.z += p0.y*h0.z; a1.w += p0.y*h0.w;
        a2.x += p0.z*h0.x; a2.y += p0.z*h0.y; a2.z += p0.z*h0.z; a2.w += p0.z*h0.w;
    }

    float4* base = reinterpret_cast<float4*>(g_agg + (size_t)w * (K_HOPS * IN_CH));
    base[lane]      = a0;
    base[32 + lane] = a1;
    base[64 + lane] = a2;
}

// ---------------------------------------------------------------------------
// Kernel 6: GEMM + max + bias.  f32x2 packed over the i-dimension:
// accumulators hold even/odd-i partial sums, folded (lo+hi) at hop end.
// a-operand: uniform LDS64 of sA[node][2ip..2ip+1] (NATURAL layout -> pure
// cp.async staging, no transpose).  b-operand: i-paired g_wp rows (pure copy).
// Both stages double-buffered: hop k+1 streams during hop k's compute.
// Block: 80 nodes x 128 outs, 256 threads -> exactly 125 blocks (N=10000).
// Smem: 2 x (40 KB sA + 64 KB sW) = 208 KB.
// ---------------------------------------------------------------------------
#define SA_F   (TN * IN_CH)           // 10240 floats
#define SW_F   (IN_CH * IN_CH)        // 16384 floats
#define STG_F  (SA_F + SW_F)          // 26624 floats per stage

__global__ __launch_bounds__(256, 1) void gemm_max_bias_kernel(
    const float* __restrict__ bias,  // [128]
    float* __restrict__ out,         // [N][128]
    int N)
{
    extern __shared__ float smem[];

    const int tid = threadIdx.x;
    const int to  = tid & 31;     // o = to*4 .. +3
    const int tw  = tid >> 5;     // warp: nodes tw*10 .. +9
    const int n0  = blockIdx.x * TN;

    // issue one stage's copies (sA then sW), caller commits
    auto issue_copy = [&](int stg, int k) {
        uint32_t da = smem_u32(smem + (size_t)stg * STG_F);
        #pragma unroll
        for (int r = 0; r < 10; r++) {
            int idx = tid + r * 256;          // 0..2559
            int nn  = idx >> 5;               // node row 0..79
            int sg  = idx & 31;               // 16B segment in row
            const float* src = g_agg + (size_t)(n0 + nn) * (K_HOPS * IN_CH)
                             + k * IN_CH + sg * 4;
            cp_async16(da + (uint32_t)idx * 16u, src);
        }
        uint32_t dw = da + SA_F * 4;
        const float* wsrc = g_wp + (size_t)k * SW_F;
        #pragma unroll
        for (int r = 0; r < 16; r++) {
            int idx = tid + r * 256;          // 0..4095
            cp_async16(dw + (uint32_t)idx * 16u, wsrc + idx * 4);
        }
        CP_COMMIT();
    };

    issue_copy(0, 0);
    issue_copy(1, 1);

    float M[10][4];
    #pragma unroll
    for (int j = 0; j < 10; j++)
        #pragma unroll
        for (int q = 0; q < 4; q++) M[j][q] = -3.0e38f;

    for (int k = 0; k < K_HOPS; k++) {
        if (k < K_HOPS - 1) { CP_WAIT(1); } else { CP_WAIT(0); }
        __syncthreads();              // stage (k&1) fully resident for all

        const float* sA = smem + (size_t)(k & 1) * STG_F;
        const uint64_t* sW = reinterpret_cast<const uint64_t*>(sA + SA_F);

        uint64_t C[10][4];
        #pragma unroll
        for (int j = 0; j < 10; j++)
            #pragma unroll
            for (int q = 0; q < 4; q++) C[j][q] = 0ull;

        const uint64_t* aBase = reinterpret_cast<const uint64_t*>(sA + tw * 10 * IN_CH);
        // aBase[j*64 + ip] = sA[node j][2ip..2ip+1]
        #pragma unroll 4
        for (int ip = 0; ip < 64; ip++) {
            uint64_t a[10];
            #pragma unroll
            for (int j = 0; j < 10; j++) a[j] = aBase[j * 64 + ip];
            const uint64_t* bp = sW + ip * 128 + to * 4;
            uint64_t b0 = bp[0], b1 = bp[1], b2 = bp[2], b3 = bp[3];
            #pragma unroll
            for (int j = 0; j < 10; j++) {
                ffma2(C[j][0], a[j], b0);
                ffma2(C[j][1], a[j], b1);
                ffma2(C[j][2], a[j], b2);
                ffma2(C[j][3], a[j], b3);
            }
        }

        __syncthreads();              // all warps done with stage (k&1)
        if (k == 0) issue_copy(0, 2); // hop2 reuses stage 0

        // fold even/odd-i partials, then running max
        #pragma unroll
        for (int j = 0; j < 10; j++)
            #pragma unroll
            for (int q = 0; q < 4; q++) {
                float lo = __uint_as_float((uint32_t)(C[j][q] & 0xFFFFFFFFull));
                float hi = __uint_as_float((uint32_t)(C[j][q] >> 32));
                M[j][q] = fmaxf(M[j][q], lo + hi);
            }
    }

    float4 bv = __ldg(reinterpret_cast<const float4*>(bias) + to);
    #pragma unroll
    for (int j = 0; j < 10; j++) {
        int node = n0 + tw * 10 + j;
        if (node < N) {
            float4 o;
            o.x = M[j][0] + bv.x;
            o.y = M[j][1] + bv.y;
            o.z = M[j][2] + bv.z;
            o.w = M[j][3] + bv.w;
            reinterpret_cast<float4*>(out + (size_t)node * IN_CH)[to] = o;
        }
    }
}

// ---------------------------------------------------------------------------
// Launch.  Inputs (metadata order): h[f32 N*128], X[f32 E*3],
// edge_index[2*E, int32 OR int64], batch_node[f32 N] (unused),
// weight[f32 3*128*128], bias[f32 128].  Output: f32 [N][128].
// ---------------------------------------------------------------------------
extern "C" void kernel_launch(void* const* d_in, const int* in_sizes, int n_in,
                              void* d_out, int out_size) {
    const float* h    = (const float*)d_in[0];
    const float* X    = (const float*)d_in[1];
    const void*  ei   = d_in[2];
    const float* W    = (const float*)d_in[4];
    const float* bias = (const float*)d_in[5];
    float*       out  = (float*)d_out;

    int N = in_sizes[0] / IN_CH;
    int E = in_sizes[1] / K_HOPS;

    const int SMEM_BYTES = 2 * STG_F * (int)sizeof(float);   // 212992
    static int smem_set = 0;
    if (!smem_set) {
        cudaFuncSetAttribute(gemm_max_bias_kernel,
                             cudaFuncAttributeMaxDynamicSharedMemorySize, SMEM_BYTES);
        smem_set = 1;
    }

    init_kernel<<<(N + 1 + 255) / 256, 256>>>(ei, E, N);
    wprep_kernel<<<(3 * 64 * IN_CH + 255) / 256, 256>>>(W);
    count_kernel<<<(E + 255) / 256, 256>>>(ei, E, N);
    scan_kernel<<<1, 1024>>>(N);
    permute_kernel<<<(E + 255) / 256, 256>>>(ei, X, E, N);
    gather_kernel<<<(N + 7) / 8, 256>>>(h, N);                      // warp per node
    gemm_max_bias_kernel<<<(N + TN - 1) / TN, 256, SMEM_BYTES>>>(bias, out, N);
}

// round 14
// speedup vs baseline: 1.0492x; 1.0492x over previous
#include <cuda_runtime.h>
#include <cstdint>

#define IN_CH  128
#define K_HOPS 3
#define MAX_N  10240
#define MAX_E  330000

#define TN     80          // nodes per GEMM block -> 125 blocks (single wave)

// Scratch (__device__ globals: allocation-guard-safe)
__device__ float  g_agg[(size_t)MAX_N * K_HOPS * IN_CH];   // [n][k][c] 15.7 MB
__device__ float4 g_packed[MAX_E];      // {x0,x1,x2, bits(dst)} sorted by src
__device__ int    g_rank[MAX_E];
__device__ int    g_cnt[MAX_N + 1];
__device__ int    g_off[MAX_N + 1];
__device__ int    g_is64;

// ---------------------------------------------------------------------------
// f32x2 packed helpers (PTX ISA 8.6, sm_100+) and cp.async helpers (Ampere+)
// ---------------------------------------------------------------------------
__device__ __forceinline__ void ffma2(uint64_t& c, uint64_t a, uint64_t b) {
    asm("fma.rn.f32x2 %0, %1, %2, %0;" : "+l"(c) : "l"(a), "l"(b));
}
__device__ __forceinline__ uint64_t bcast2(float v) {
    uint64_t r;
    asm("mov.b64 %0, {%1, %1};" : "=l"(r) : "r"(__float_as_uint(v)));
    return r;
}
__device__ __forceinline__ uint32_t smem_u32(const void* p) {
    uint32_t a;
    asm("{ .reg .u64 t; cvta.to.shared.u64 t, %1; cvt.u32.u64 %0, t; }"
        : "=r"(a) : "l"(p));
    return a;
}
__device__ __forceinline__ void cp_async16(uint32_t dst, const void* src) {
    asm volatile("cp.async.ca.shared.global [%0], [%1], 16;"
                 :: "r"(dst), "l"(src) : "memory");
}
#define CP_COMMIT()  asm volatile("cp.async.commit_group;" ::: "memory")
#define CP_WAIT(n)   asm volatile("cp.async.wait_group %0;" :: "n"(n) : "memory")

// ---------------------------------------------------------------------------
// Kernel 1: zero counts + detect edge_index dtype (JAX may emit int32 even
// though the reference asks for int64).
// ---------------------------------------------------------------------------
__global__ void init_kernel(const void* ei, int E, int N) {
    int i = blockIdx.x * blockDim.x + threadIdx.x;
    if (i <= N) g_cnt[i] = 0;
    if (i == 0) {
        const long long* p64 = (const long long*)ei;
        int ok = 1;
        int cnt = (E < 64) ? E : 64;
        for (int j = 0; j < cnt; j++) {
            long long v = p64[j];
            if (v < 0 || v >= (long long)N) { ok = 0; break; }
        }
        g_is64 = ok;
    }
}

// ---------------------------------------------------------------------------
// Kernel 2: histogram of src + per-edge rank (atomic kept out of permute)
// ---------------------------------------------------------------------------
__global__ __launch_bounds__(256) void count_kernel(const void* __restrict__ ei,
                                                    int E, int N) {
    int e = blockIdx.x * blockDim.x + threadIdx.x;
    if (e >= E) return;
    int src = g_is64 ? (int)__ldg((const long long*)ei + e)
                     : __ldg((const int*)ei + e);
    if ((unsigned)src < (unsigned)N)
        g_rank[e] = atomicAdd(&g_cnt[src], 1);
}

// ---------------------------------------------------------------------------
// Kernel 3: exclusive scan, warp-shuffle two-level (2 barriers total).
// 1024 threads, each owns a chunk of ceil(N/1024) counts.
// ---------------------------------------------------------------------------
__global__ __launch_bounds__(1024) void scan_kernel(int N) {
    __shared__ int wsum[32];
    int t    = threadIdx.x;
    int lane = t & 31;
    int wrp  = t >> 5;

    int chunk = (N + 1023) / 1024;
    int b0 = t * chunk;
    int b1 = b0 + chunk; if (b1 > N) b1 = N;

    // local loads (independent) + local total
    int loc[16];                       // chunk <= 16 for N <= 16384
    int s = 0;
    for (int i = b0; i < b1; i++) { int c = __ldg(&g_cnt[i]); loc[i - b0] = c; s += c; }

    // warp inclusive scan of per-thread totals
    int inc = s;
    #pragma unroll
    for (int d = 1; d < 32; d <<= 1) {
        int v = __shfl_up_sync(0xFFFFFFFFu, inc, d);
        if (lane >= d) inc += v;
    }
    if (lane == 31) wsum[wrp] = inc;
    __syncthreads();

    // warp 0 scans the 32 warp totals (exclusive)
    if (wrp == 0) {
        int v = wsum[lane];
        int wi = v;
        #pragma unroll
        for (int d = 1; d < 32; d <<= 1) {
            int u = __shfl_up_sync(0xFFFFFFFFu, wi, d);
            if (lane >= d) wi += u;
        }
        wsum[lane] = wi - v;           // exclusive
    }
    __syncthreads();

    int base = wsum[wrp] + (inc - s);  // exclusive prefix for this thread
    int run = base;
    for (int i = b0; i < b1; i++) { g_off[i] = run; run += loc[i - b0]; }
    if (t == 1023) g_off[N] = run;
}

// ---------------------------------------------------------------------------
// Kernel 4: permute edges into src-sorted packed records (atomic-free)
// ---------------------------------------------------------------------------
__global__ __launch_bounds__(256) void permute_kernel(const void* __restrict__ ei,
                                                      const float* __restrict__ X,
                                                      int E, int N) {
    int e = blockIdx.x * blockDim.x + threadIdx.x;
    if (e >= E) return;
    int src, dst;
    if (g_is64) {
        const long long* p = (const long long*)ei;
        src = (int)__ldg(p + e);
        dst = (int)__ldg(p + (size_t)E + e);
    } else {
        const int* p = (const int*)ei;
        src = __ldg(p + e);
        dst = __ldg(p + (size_t)E + e);
    }
    if ((unsigned)src >= (unsigned)N || (unsigned)dst >= (unsigned)N) return;
    float x0 = __ldg(X + (size_t)e * 3 + 0);
    float x1 = __ldg(X + (size_t)e * 3 + 1);
    float x2 = __ldg(X + (size_t)e * 3 + 2);
    int pos = __ldg(&g_off[src]) + __ldg(&g_rank[e]);
    g_packed[pos] = make_float4(x0, x1, x2, __int_as_float(dst));
}

// ---------------------------------------------------------------------------
// Kernel 5: gather-aggregate.  One warp per node; lane owns 4 channels.
// 4-edge unroll for MLP.  Writes every node -> no zero pass needed.
// ---------------------------------------------------------------------------
__global__ __launch_bounds__(256) void gather_kernel(
    const float* __restrict__ h, int N) {
    int w    = (blockIdx.x * blockDim.x + threadIdx.x) >> 5;
    int lane = threadIdx.x & 31;
    if (w >= N) return;

    int beg = __ldg(&g_off[w]);
    int end = __ldg(&g_off[w + 1]);

    float4 a0 = make_float4(0.f, 0.f, 0.f, 0.f);
    float4 a1 = a0, a2 = a0;

    int e = beg;
    for (; e + 3 < end; e += 4) {
        float4 p[4];
        #pragma unroll
        for (int j = 0; j < 4; j++) p[j] = __ldg(&g_packed[e + j]);
        float4 hv[4];
        #pragma unroll
        for (int j = 0; j < 4; j++) {
            int d = __float_as_int(p[j].w);
            hv[j] = __ldg(reinterpret_cast<const float4*>(h + (size_t)d * IN_CH) + lane);
        }
        #pragma unroll
        for (int j = 0; j < 4; j++) {
            a0.x += p[j].x*hv[j].x; a0.y += p[j].x*hv[j].y; a0.z += p[j].x*hv[j].z; a0.w += p[j].x*hv[j].w;
            a1.x += p[j].y*hv[j].x; a1.y += p[j].y*hv[j].y; a1.z += p[j].y*hv[j].z; a1.w += p[j].y*hv[j].w;
            a2.x += p[j].z*hv[j].x; a2.y += p[j].z*hv[j].y; a2.z += p[j].z*hv[j].z; a2.w += p[j].z*hv[j].w;
        }
    }
    for (; e < end; e++) {
        float4 p0 = __ldg(&g_packed[e]);
        int d0 = __float_as_int(p0.w);
        float4 h0 = __ldg(reinterpret_cast<const float4*>(h + (size_t)d0 * IN_CH) + lane);
        a0.x += p0.x*h0.x; a0.y += p0.x*h0.y; a0.z += p0.x*h0.z; a0.w += p0.x*h0.w;
        a1.x += p0.y*h0.x; a1.y += p0.y*h0.y; a1.z += p0.y*h0.z; a1.w += p0.y*h0.w;
        a2.x += p0.z*h0.x; a2.y += p0.z*h0.y; a2.z += p0.z*h0.z; a2.w += p0.z*h0.w;
    }

    float4* base = reinterpret_cast<float4*>(g_agg + (size_t)w * (K_HOPS * IN_CH));
    base[lane]      = a0;
    base[32 + lane] = a1;
    base[64 + lane] = a2;
}

// ---------------------------------------------------------------------------
// Kernel 6: fused per-hop GEMM + max + bias, f32x2 FMA, cp.async W pipeline.
//   out[n,o] = max_k( sum_i agg[n,k,i] * W[k,i,o] ) + bias[o]
// Block: 80 nodes x 128 outs, 256 threads -> 125 blocks = single wave.
// sW double-buffered via cp.async (next hop's W streams during compute).
// sA transposed [i][node] staged with LDG+STS.  Smem 168 KB.
// ---------------------------------------------------------------------------
__global__ __launch_bounds__(256, 1) void gemm_max_bias_kernel(
    const float* __restrict__ W,     // [3][128][128]
    const float* __restrict__ bias,  // [128]
    float* __restrict__ out,         // [N][128]
    int N)
{
    extern __shared__ float smem[];
    float* sA  = smem;                       // [128][TN]
    float* sWb = smem + IN_CH * TN;          // two [128][128] buffers

    const int tid = threadIdx.x;
    const int to  = tid & 31;     // o = to*4 .. +3
    const int tw  = tid >> 5;     // warp: nodes tw*10 .. +9
    const int n0  = blockIdx.x * TN;

    // Prologue: prefetch hop 0's W into buffer 0
    {
        uint32_t dst = smem_u32(sWb);
        const float4* src = reinterpret_cast<const float4*>(W);
        #pragma unroll
        for (int r = 0; r < 16; r++)
            cp_async16(dst + (tid + r * 256) * 16, src + tid + r * 256);
        CP_COMMIT();
    }

    float M[10][4];
    #pragma unroll
    for (int j = 0; j < 10; j++)
        #pragma unroll
        for (int q = 0; q < 4; q++) M[j][q] = -3.0e38f;

    for (int k = 0; k < K_HOPS; k++) {
        __syncthreads();   // previous hop's readers done (sA + its sW buffer)

        // Stage sA: 80 nodes x 128 i, transposed.  2560 float4 loads.
        #pragma unroll
        for (int r = 0; r < 10; r++) {
            int idx = tid + r * 256;      // 0..2559
            int nn  = idx % TN;
            int ig  = idx / TN;           // 0..31
            int node = n0 + nn;
            float4 v = make_float4(0.f, 0.f, 0.f, 0.f);
            if (node < N)
                v = __ldg(reinterpret_cast<const float4*>(
                        g_agg + (size_t)node * (K_HOPS * IN_CH) + k * IN_CH + ig * 4));
            sA[(ig * 4 + 0) * TN + nn] = v.x;
            sA[(ig * 4 + 1) * TN + nn] = v.y;
            sA[(ig * 4 + 2) * TN + nn] = v.z;
            sA[(ig * 4 + 3) * TN + nn] = v.w;
        }

        // Kick off next hop's W copy into the other buffer (fully async)
        if (k < K_HOPS - 1) {
            uint32_t dst = smem_u32(sWb + ((k + 1) & 1) * IN_CH * IN_CH);
            const float4* src = reinterpret_cast<const float4*>(
                W + (size_t)(k + 1) * IN_CH * IN_CH);
            #pragma unroll
            for (int r = 0; r < 16; r++)
                cp_async16(dst + (tid + r * 256) * 16, src + tid + r * 256);
            CP_COMMIT();
            CP_WAIT(1);    // this hop's buffer (older group) complete
        } else {
            CP_WAIT(0);    // last buffer complete
        }
        __syncthreads();

        const float* sW = sWb + (k & 1) * IN_CH * IN_CH;

        uint64_t C[5][4];
        #pragma unroll
        for (int p = 0; p < 5; p++)
            #pragma unroll
            for (int q = 0; q < 4; q++) C[p][q] = 0ull;

        const float* aRow0 = sA + tw * 10;   // 40*tw bytes: 8B-aligned
        #pragma unroll 8
        for (int i = 0; i < IN_CH; i++) {
            const uint64_t* ap = reinterpret_cast<const uint64_t*>(aRow0 + i * TN);
            uint64_t a0 = ap[0], a1 = ap[1], a2 = ap[2], a3 = ap[3], a4 = ap[4];
            float4 b = *reinterpret_cast<const float4*>(&sW[i * IN_CH + to * 4]);
            uint64_t b0 = bcast2(b.x), b1 = bcast2(b.y), b2 = bcast2(b.z), b3 = bcast2(b.w);
            ffma2(C[0][0], a0, b0); ffma2(C[0][1], a0, b1); ffma2(C[0][2], a0, b2); ffma2(C[0][3], a0, b3);
            ffma2(C[1][0], a1, b0); ffma2(C[1][1], a1, b1); ffma2(C[1][2], a1, b2); ffma2(C[1][3], a1, b3);
            ffma2(C[2][0], a2, b0); ffma2(C[2][1], a2, b1); ffma2(C[2][2], a2, b2); ffma2(C[2][3], a2, b3);
            ffma2(C[3][0], a3, b0); ffma2(C[3][1], a3, b1); ffma2(C[3][2], a3, b2); ffma2(C[3][3], a3, b3);
            ffma2(C[4][0], a4, b0); ffma2(C[4][1], a4, b1); ffma2(C[4][2], a4, b2); ffma2(C[4][3], a4, b3);
        }

        // Fold packed pairs into running max (lo half = even node)
        #pragma unroll
        for (int p = 0; p < 5; p++)
            #pragma unroll
            for (int q = 0; q < 4; q++) {
                float lo = __uint_as_float((uint32_t)(C[p][q] & 0xFFFFFFFFull));
                float hi = __uint_as_float((uint32_t)(C[p][q] >> 32));
                M[2 * p][q]     = fmaxf(M[2 * p][q], lo);
                M[2 * p + 1][q] = fmaxf(M[2 * p + 1][q], hi);
            }
    }

    float4 bv = __ldg(reinterpret_cast<const float4*>(bias) + to);
    #pragma unroll
    for (int j = 0; j < 10; j++) {
        int node = n0 + tw * 10 + j;
        if (node < N) {
            float4 o;
            o.x = M[j][0] + bv.x;
            o.y = M[j][1] + bv.y;
            o.z = M[j][2] + bv.z;
            o.w = M[j][3] + bv.w;
            reinterpret_cast<float4*>(out + (size_t)node * IN_CH)[to] = o;
        }
    }
}

// ---------------------------------------------------------------------------
// Launch.  Inputs (metadata order): h[f32 N*128], X[f32 E*3],
// edge_index[2*E, int32 OR int64], batch_node[f32 N] (unused),
// weight[f32 3*128*128], bias[f32 128].  Output: f32 [N][128].
// ---------------------------------------------------------------------------
extern "C" void kernel_launch(void* const* d_in, const int* in_sizes, int n_in,
                              void* d_out, int out_size) {
    const float* h    = (const float*)d_in[0];
    const float* X    = (const float*)d_in[1];
    const void*  ei   = d_in[2];
    const float* W    = (const float*)d_in[4];
    const float* bias = (const float*)d_in[5];
    float*       out  = (float*)d_out;

    int N = in_sizes[0] / IN_CH;
    int E = in_sizes[1] / K_HOPS;

    const int SMEM_BYTES = (IN_CH * TN + 2 * IN_CH * IN_CH) * (int)sizeof(float); // 172032
    static int smem_set = 0;
    if (!smem_set) {
        cudaFuncSetAttribute(gemm_max_bias_kernel,
                             cudaFuncAttributeMaxDynamicSharedMemorySize, SMEM_BYTES);
        smem_set = 1;
    }

    init_kernel<<<(N + 1 + 255) / 256, 256>>>(ei, E, N);
    count_kernel<<<(E + 255) / 256, 256>>>(ei, E, N);
    scan_kernel<<<1, 1024>>>(N);
    permute_kernel<<<(E + 255) / 256, 256>>>(ei, X, E, N);
    gather_kernel<<<(N + 7) / 8, 256>>>(h, N);                      // warp per node
    gemm_max_bias_kernel<<<(N + TN - 1) / TN, 256, SMEM_BYTES>>>(W, bias, out, N);
}

// round 15
// speedup vs baseline: 1.0555x; 1.0061x over previous
#include <cuda_runtime.h>
#include <cstdint>

#define IN_CH  128
#define K_HOPS 3
#define MAX_N  10240
#define MAX_E  330000

#define TN     80          // nodes per GEMM block -> 125 blocks (single wave)

// Scratch (__device__ globals: allocation-guard-safe)
__device__ float  g_agg[(size_t)MAX_N * K_HOPS * IN_CH];   // [n][k][c] 15.7 MB
__device__ float4 g_packed[MAX_E];      // {x0,x1,x2, bits(dst)} sorted by src
__device__ int    g_rank[MAX_E];
__device__ int    g_cnt[MAX_N + 1];
__device__ int    g_off[MAX_N + 1];
__device__ int    g_is64;

// ---------------------------------------------------------------------------
// f32x2 packed helpers (PTX ISA 8.6, sm_100+) and cp.async helpers (Ampere+)
// ---------------------------------------------------------------------------
__device__ __forceinline__ void ffma2(uint64_t& c, uint64_t a, uint64_t b) {
    asm("fma.rn.f32x2 %0, %1, %2, %0;" : "+l"(c) : "l"(a), "l"(b));
}
__device__ __forceinline__ uint64_t bcast2(float v) {
    uint64_t r;
    asm("mov.b64 %0, {%1, %1};" : "=l"(r) : "r"(__float_as_uint(v)));
    return r;
}
__device__ __forceinline__ uint32_t smem_u32(const void* p) {
    uint32_t a;
    asm("{ .reg .u64 t; cvta.to.shared.u64 t, %1; cvt.u32.u64 %0, t; }"
        : "=r"(a) : "l"(p));
    return a;
}
__device__ __forceinline__ void cp_async16(uint32_t dst, const void* src) {
    asm volatile("cp.async.ca.shared.global [%0], [%1], 16;"
                 :: "r"(dst), "l"(src) : "memory");
}
#define CP_COMMIT()  asm volatile("cp.async.commit_group;" ::: "memory")
#define CP_WAIT(n)   asm volatile("cp.async.wait_group %0;" :: "n"(n) : "memory")

// ---------------------------------------------------------------------------
// Kernel 1: zero counts + detect edge_index dtype (JAX may emit int32 even
// though the reference asks for int64).
// ---------------------------------------------------------------------------
__global__ void init_kernel(const void* ei, int E, int N) {
    int i = blockIdx.x * blockDim.x + threadIdx.x;
    if (i <= N) g_cnt[i] = 0;
    if (i == 0) {
        const long long* p64 = (const long long*)ei;
        int ok = 1;
        int cnt = (E < 64) ? E : 64;
        for (int j = 0; j < cnt; j++) {
            long long v = p64[j];
            if (v < 0 || v >= (long long)N) { ok = 0; break; }
        }
        g_is64 = ok;
    }
}

// ---------------------------------------------------------------------------
// Kernel 2: histogram of src + per-edge rank (atomic kept out of permute)
// ---------------------------------------------------------------------------
__global__ __launch_bounds__(256) void count_kernel(const void* __restrict__ ei,
                                                    int E, int N) {
    int e = blockIdx.x * blockDim.x + threadIdx.x;
    if (e >= E) return;
    int src = g_is64 ? (int)__ldg((const long long*)ei + e)
                     : __ldg((const int*)ei + e);
    if ((unsigned)src < (unsigned)N)
        g_rank[e] = atomicAdd(&g_cnt[src], 1);
}

// ---------------------------------------------------------------------------
// Kernel 3: exclusive scan, warp-shuffle two-level (2 barriers total)
// ---------------------------------------------------------------------------
__global__ __launch_bounds__(1024) void scan_kernel(int N) {
    __shared__ int wsum[32];
    int t    = threadIdx.x;
    int lane = t & 31;
    int wrp  = t >> 5;

    int chunk = (N + 1023) / 1024;
    int b0 = t * chunk;
    int b1 = b0 + chunk; if (b1 > N) b1 = N;

    int loc[16];
    int s = 0;
    for (int i = b0; i < b1; i++) { int c = __ldg(&g_cnt[i]); loc[i - b0] = c; s += c; }

    int inc = s;
    #pragma unroll
    for (int d = 1; d < 32; d <<= 1) {
        int v = __shfl_up_sync(0xFFFFFFFFu, inc, d);
        if (lane >= d) inc += v;
    }
    if (lane == 31) wsum[wrp] = inc;
    __syncthreads();

    if (wrp == 0) {
        int v = wsum[lane];
        int wi = v;
        #pragma unroll
        for (int d = 1; d < 32; d <<= 1) {
            int u = __shfl_up_sync(0xFFFFFFFFu, wi, d);
            if (lane >= d) wi += u;
        }
        wsum[lane] = wi - v;
    }
    __syncthreads();

    int run = wsum[wrp] + (inc - s);
    for (int i = b0; i < b1; i++) { g_off[i] = run; run += loc[i - b0]; }
    if (t == 1023) g_off[N] = run;
}

// ---------------------------------------------------------------------------
// Kernel 4: permute edges into src-sorted packed records (atomic-free)
// ---------------------------------------------------------------------------
__global__ __launch_bounds__(256) void permute_kernel(const void* __restrict__ ei,
                                                      const float* __restrict__ X,
                                                      int E, int N) {
    int e = blockIdx.x * blockDim.x + threadIdx.x;
    if (e >= E) return;
    int src, dst;
    if (g_is64) {
        const long long* p = (const long long*)ei;
        src = (int)__ldg(p + e);
        dst = (int)__ldg(p + (size_t)E + e);
    } else {
        const int* p = (const int*)ei;
        src = __ldg(p + e);
        dst = __ldg(p + (size_t)E + e);
    }
    if ((unsigned)src >= (unsigned)N || (unsigned)dst >= (unsigned)N) return;
    float x0 = __ldg(X + (size_t)e * 3 + 0);
    float x1 = __ldg(X + (size_t)e * 3 + 1);
    float x2 = __ldg(X + (size_t)e * 3 + 2);
    int pos = __ldg(&g_off[src]) + __ldg(&g_rank[e]);
    g_packed[pos] = make_float4(x0, x1, x2, __int_as_float(dst));
}

// ---------------------------------------------------------------------------
// Kernel 5: gather-aggregate.  One warp per node; lane owns 4 channels.
// ---------------------------------------------------------------------------
__global__ __launch_bounds__(256) void gather_kernel(
    const float* __restrict__ h, int N) {
    int w    = (blockIdx.x * blockDim.x + threadIdx.x) >> 5;
    int lane = threadIdx.x & 31;
    if (w >= N) return;

    int beg = __ldg(&g_off[w]);
    int end = __ldg(&g_off[w + 1]);

    float4 a0 = make_float4(0.f, 0.f, 0.f, 0.f);
    float4 a1 = a0, a2 = a0;

    int e = beg;
    for (; e + 3 < end; e += 4) {
        float4 p[4];
        #pragma unroll
        for (int j = 0; j < 4; j++) p[j] = __ldg(&g_packed[e + j]);
        float4 hv[4];
        #pragma unroll
        for (int j = 0; j < 4; j++) {
            int d = __float_as_int(p[j].w);
            hv[j] = __ldg(reinterpret_cast<const float4*>(h + (size_t)d * IN_CH) + lane);
        }
        #pragma unroll
        for (int j = 0; j < 4; j++) {
            a0.x += p[j].x*hv[j].x; a0.y += p[j].x*hv[j].y; a0.z += p[j].x*hv[j].z; a0.w += p[j].x*hv[j].w;
            a1.x += p[j].y*hv[j].x; a1.y += p[j].y*hv[j].y; a1.z += p[j].y*hv[j].z; a1.w += p[j].y*hv[j].w;
            a2.x += p[j].z*hv[j].x; a2.y += p[j].z*hv[j].y; a2.z += p[j].z*hv[j].z; a2.w += p[j].z*hv[j].w;
        }
    }
    for (; e < end; e++) {
        float4 p0 = __ldg(&g_packed[e]);
        int d0 = __float_as_int(p0.w);
        float4 h0 = __ldg(reinterpret_cast<const float4*>(h + (size_t)d0 * IN_CH) + lane);
        a0.x += p0.x*h0.x; a0.y += p0.x*h0.y; a0.z += p0.x*h0.z; a0.w += p0.x*h0.w;
        a1.x += p0.y*h0.x; a1.y += p0.y*h0.y; a1.z += p0.y*h0.z; a1.w += p0.y*h0.w;
        a2.x += p0.z*h0.x; a2.y += p0.z*h0.y; a2.z += p0.z*h0.z; a2.w += p0.z*h0.w;
    }

    float4* base = reinterpret_cast<float4*>(g_agg + (size_t)w * (K_HOPS * IN_CH));
    base[lane]      = a0;
    base[32 + lane] = a1;
    base[64 + lane] = a2;
}

// ---------------------------------------------------------------------------
// Kernel 6: GEMM + max + bias.  f32x2 FMA; sA staged ASYNC in natural layout
// with XOR-swizzled segments, transposed smem->smem conflict-free; sW
// double-buffered cp.async.  Hop k+1 streams during hop k's compute.
// Smem: sAT 40K + sAnat 40K + 2x sW 64K = 208 KB.
// ---------------------------------------------------------------------------
#define OFF_AT  0                      // [128][TN] transposed, compute operand
#define OFF_NAT (IN_CH * TN)           // [TN][128] natural, swizzled segments
#define OFF_W   (2 * IN_CH * TN)       // two [128][128] buffers
#define GEMM_SMEM_F (2 * IN_CH * TN + 2 * IN_CH * IN_CH)   // 53248 floats

__global__ __launch_bounds__(256, 1) void gemm_max_bias_kernel(
    const float* __restrict__ W,     // [3][128][128]
    const float* __restrict__ bias,  // [128]
    float* __restrict__ out,         // [N][128]
    int N)
{
    extern __shared__ float smem[];
    float* sAT  = smem + OFF_AT;
    float* sAn  = smem + OFF_NAT;
    float* sWb  = smem + OFF_W;

    const int tid = threadIdx.x;
    const int to  = tid & 31;     // o = to*4 .. +3
    const int tw  = tid >> 5;     // warp: nodes tw*10 .. +9
    const int n0  = blockIdx.x * TN;

    const uint32_t aNatBase = smem_u32(sAn);
    const uint32_t wBase    = smem_u32(sWb);

    // cp.async sA hop k into sAn (natural rows, XOR-swizzled 16B segments)
    auto issue_sA = [&](int k) {
        #pragma unroll
        for (int r = 0; r < 10; r++) {
            int idx = tid + r * 256;          // 0..2559
            int nn  = idx >> 5;               // row 0..79
            int p   = idx & 31;               // physical seg
            int sl  = p ^ (nn & 7);           // logical seg (swizzle)
            const float* src = g_agg + (size_t)(n0 + nn) * (K_HOPS * IN_CH)
                             + k * IN_CH + sl * 4;
            cp_async16(aNatBase + (uint32_t)idx * 16u, src);
        }
    };
    auto issue_sW = [&](int k, int buf) {
        uint32_t dst = wBase + (uint32_t)buf * IN_CH * IN_CH * 4u;
        const float4* src = reinterpret_cast<const float4*>(
            W + (size_t)k * IN_CH * IN_CH);
        #pragma unroll
        for (int r = 0; r < 16; r++)
            cp_async16(dst + (tid + r * 256) * 16, src + tid + r * 256);
    };

    // Prologue: G0 = {sA0, W0}; G1 = {W1}
    issue_sA(0); issue_sW(0, 0); CP_COMMIT();
    issue_sW(1, 1); CP_COMMIT();

    float M[10][4];
    #pragma unroll
    for (int j = 0; j < 10; j++)
        #pragma unroll
        for (int q = 0; q < 4; q++) M[j][q] = -3.0e38f;

    for (int k = 0; k < K_HOPS; k++) {
        if (k == 0) { CP_WAIT(1); } else { CP_WAIT(0); }
        __syncthreads();              // staged data visible to all; prev compute done

        // Transpose sAn -> sAT (conflict-free thanks to segment swizzle)
        #pragma unroll
        for (int r = 0; r < 10; r++) {
            int idx = tid + r * 256;      // 0..2559
            int nn  = idx % TN;           // lanes span nn
            int sl  = idx / TN;           // logical seg 0..31
            float4 v = *reinterpret_cast<const float4*>(
                sAn + nn * IN_CH + (sl ^ (nn & 7)) * 4);
            sAT[(sl * 4 + 0) * TN + nn] = v.x;
            sAT[(sl * 4 + 1) * TN + nn] = v.y;
            sAT[(sl * 4 + 2) * TN + nn] = v.z;
            sAT[(sl * 4 + 3) * TN + nn] = v.w;
        }
        __syncthreads();              // sAT ready; sAn free for refill

        if (k == 0)      { issue_sA(1); CP_COMMIT(); }
        else if (k == 1) { issue_sA(2); issue_sW(2, 0); CP_COMMIT(); }

        const float* sW = sWb + (size_t)(k & 1) * IN_CH * IN_CH;

        uint64_t C[5][4];
        #pragma unroll
        for (int p = 0; p < 5; p++)
            #pragma unroll
            for (int q = 0; q < 4; q++) C[p][q] = 0ull;

        const float* aRow0 = sAT + tw * 10;   // 40B-aligned
        #pragma unroll 8
        for (int i = 0; i < IN_CH; i++) {
            const uint64_t* ap = reinterpret_cast<const uint64_t*>(aRow0 + i * TN);
            uint64_t a0 = ap[0], a1 = ap[1], a2 = ap[2], a3 = ap[3], a4 = ap[4];
            float4 b = *reinterpret_cast<const float4*>(&sW[i * IN_CH + to * 4]);
            uint64_t b0 = bcast2(b.x), b1 = bcast2(b.y), b2 = bcast2(b.z), b3 = bcast2(b.w);
            ffma2(C[0][0], a0, b0); ffma2(C[0][1], a0, b1); ffma2(C[0][2], a0, b2); ffma2(C[0][3], a0, b3);
            ffma2(C[1][0], a1, b0); ffma2(C[1][1], a1, b1); ffma2(C[1][2], a1, b2); ffma2(C[1][3], a1, b3);
            ffma2(C[2][0], a2, b0); ffma2(C[2][1], a2, b1); ffma2(C[2][2], a2, b2); ffma2(C[2][3], a2, b3);
            ffma2(C[3][0], a3, b0); ffma2(C[3][1], a3, b1); ffma2(C[3][2], a3, b2); ffma2(C[3][3], a3, b3);
            ffma2(C[4][0], a4, b0); ffma2(C[4][1], a4, b1); ffma2(C[4][2], a4, b2); ffma2(C[4][3], a4, b3);
        }

        #pragma unroll
        for (int p = 0; p < 5; p++)
            #pragma unroll
            for (int q = 0; q < 4; q++) {
                float lo = __uint_as_float((uint32_t)(C[p][q] & 0xFFFFFFFFull));
                float hi = __uint_as_float((uint32_t)(C[p][q] >> 32));
                M[2 * p][q]     = fmaxf(M[2 * p][q], lo);
                M[2 * p + 1][q] = fmaxf(M[2 * p + 1][q], hi);
            }
    }

    float4 bv = __ldg(reinterpret_cast<const float4*>(bias) + to);
    #pragma unroll
    for (int j = 0; j < 10; j++) {
        int node = n0 + tw * 10 + j;
        if (node < N) {
            float4 o;
            o.x = M[j][0] + bv.x;
            o.y = M[j][1] + bv.y;
            o.z = M[j][2] + bv.z;
            o.w = M[j][3] + bv.w;
            reinterpret_cast<float4*>(out + (size_t)node * IN_CH)[to] = o;
        }
    }
}

// ---------------------------------------------------------------------------
// Launch.  Inputs (metadata order): h[f32 N*128], X[f32 E*3],
// edge_index[2*E, int32 OR int64], batch_node[f32 N] (unused),
// weight[f32 3*128*128], bias[f32 128].  Output: f32 [N][128].
// ---------------------------------------------------------------------------
extern "C" void kernel_launch(void* const* d_in, const int* in_sizes, int n_in,
                              void* d_out, int out_size) {
    const float* h    = (const float*)d_in[0];
    const float* X    = (const float*)d_in[1];
    const void*  ei   = d_in[2];
    const float* W    = (const float*)d_in[4];
    const float* bias = (const float*)d_in[5];
    float*       out  = (float*)d_out;

    int N = in_sizes[0] / IN_CH;
    int E = in_sizes[1] / K_HOPS;

    const int SMEM_BYTES = GEMM_SMEM_F * (int)sizeof(float);   // 212992
    static int smem_set = 0;
    if (!smem_set) {
        cudaFuncSetAttribute(gemm_max_bias_kernel,
                             cudaFuncAttributeMaxDynamicSharedMemorySize, SMEM_BYTES);
        smem_set = 1;
    }

    init_kernel<<<(N + 1 + 255) / 256, 256>>>(ei, E, N);
    count_kernel<<<(E + 255) / 256, 256>>>(ei, E, N);
    scan_kernel<<<1, 1024>>>(N);
    permute_kernel<<<(E + 255) / 256, 256>>>(ei, X, E, N);
    gather_kernel<<<(N + 7) / 8, 256>>>(h, N);                      // warp per node
    gemm_max_bias_kernel<<<(N + TN - 1) / TN, 256, SMEM_BYTES>>>(W, bias, out, N);
}